// round 1
// baseline (speedup 1.0000x reference)
#include <cuda_runtime.h>
#include <math_constants.h>

// ---------------------------------------------------------------------------
// APPM: 13-ratio sliding-window average pooling over a 112x112 feature map,
// followed by 3-group greedy NMS (picks 2/3/2, IoU thresh 0.25).
//
// Strategy: per-image summed-area table (SAT, 113x113 floats = 51KB) in shared
// memory. Window sum = 4 SAT reads. One CTA per image does:
//   (1) build SAT, (2) stream all 96981 window scores to gmem (coalesced),
//   (3) run the 3 NMS groups from the smem SAT (coords derived analytically).
//
// Output layout (float32):
//   [0,                1792)  proposalN_indices  (256 x 7), stored as float
//   [1792,             3584)  proposalN_windows_scores (256 x 7)
//   [3584, 3584+256*96981)    window_scores (256 x 96981)
// ---------------------------------------------------------------------------

#define FEAT   112
#define SATN   113            // SAT dimension (1 pad row/col of zeros)
#define NRAT   13
#define NBATCH 256
#define NTOTAL 96981
#define PROPN  7
#define NTHREADS 1024

__global__ void __launch_bounds__(NTHREADS, 2)
appm_kernel(const float* __restrict__ x, float* __restrict__ out)
{
    // ---- compile-time tables -------------------------------------------
    constexpr int RH[NRAT] = {16,12,20,24,20,28,32,24,40,28,40,28,36};
    constexpr int RW[NRAT] = {16,20,12,24,28,20,32,40,24,40,28,36,28};
    constexpr int BASE[NRAT] = {0, 9409, 18802, 28195, 36116, 44021, 51926,
                                58487, 64984, 71481, 77686, 83891, 90436};
    // groups: ratios [0,3), [3,6), [6,13); picks 2,3,2; thresh 0.25
    constexpr int G0[3]     = {0, 3, 6};
    constexpr int G1[3]     = {3, 6, 13};
    constexpr int NPICK[3]  = {2, 3, 2};
    constexpr int OUTOFF[3] = {0, 2, 5};

    extern __shared__ float S[];  // SATN*SATN summed-area table

    const int tid  = threadIdx.x;
    const int b    = blockIdx.x;
    const int lane = tid & 31;
    const int warp = tid >> 5;

    const float* __restrict__ xb = x + (size_t)b * (FEAT * FEAT);

    // ---- (1) fill SAT buffer: zero pad row/col, copy x --------------------
    for (int k = tid; k < SATN * SATN; k += NTHREADS) {
        int i = k / SATN;
        int j = k - i * SATN;
        S[k] = (i > 0 && j > 0) ? xb[(i - 1) * FEAT + (j - 1)] : 0.0f;
    }
    __syncthreads();

    // row-wise inclusive prefix (thread per row). stride 113 is odd -> no
    // bank conflicts across threads at the same j.
    if (tid < SATN) {
        float acc = 0.0f;
        float* row = S + tid * SATN;
        #pragma unroll 4
        for (int j = 1; j < SATN; j++) { acc += row[j]; row[j] = acc; }
    }
    __syncthreads();

    // column-wise inclusive prefix (thread per column). consecutive threads
    // hit consecutive addresses -> conflict-free.
    if (tid < SATN) {
        float acc = 0.0f;
        #pragma unroll 4
        for (int i = 1; i < SATN; i++) {
            acc += S[i * SATN + tid];
            S[i * SATN + tid] = acc;
        }
    }
    __syncthreads();

    // ---- (2) window scores -> gmem (coalesced) ---------------------------
    float* __restrict__ ws = out + 2 * (NBATCH * PROPN) + (size_t)b * NTOTAL;

    #pragma unroll
    for (int r = 0; r < NRAT; r++) {
        const int rh = RH[r], rw = RW[r];
        const int nr = SATN - rh, nc = SATN - rw;
        const int n  = nr * nc;
        const float inv = 1.0f / (float)(rh * rw);
        const int base = BASE[r];
        for (int i = tid; i < n; i += NTHREADS) {
            int xi = i / nc;              // nc is compile-time -> mul/shift
            int yi = i - xi * nc;
            float s = S[(xi + rh) * SATN + (yi + rw)]
                    - S[xi * SATN + (yi + rw)]
                    - S[(xi + rh) * SATN + yi]
                    + S[xi * SATN + yi];
            ws[base + i] = s * inv;
        }
    }
    // SAT is read-only from here; no sync needed before NMS reads it.

    // ---- (3) per-group greedy NMS ----------------------------------------
    __shared__ float selx0[3], sely0[3], selx1[3], sely1[3], selarea[3];
    __shared__ float red_s[32];
    __shared__ int   red_i[32];

    const float thresh = 0.25f;

    #pragma unroll
    for (int g = 0; g < 3; g++) {
        const int np = NPICK[g];
        for (int pick = 0; pick < np; pick++) {
            float best = -CUDART_INF_F;
            int   bidx = 0x7fffffff;

            #pragma unroll
            for (int r = G0[g]; r < G1[g]; r++) {
                const int rh = RH[r], rw = RW[r];
                const int nr = SATN - rh, nc = SATN - rw;
                const int n  = nr * nc;
                const float inv = 1.0f / (float)(rh * rw);
                const float fh = 4.0f * rh, fw = 4.0f * rw;
                const int base = BASE[r];
                for (int i = tid; i < n; i += NTHREADS) {
                    int xi = i / nc;
                    int yi = i - xi * nc;
                    float s = (S[(xi + rh) * SATN + (yi + rw)]
                             - S[xi * SATN + (yi + rw)]
                             - S[(xi + rh) * SATN + yi]
                             + S[xi * SATN + yi]) * inv;
                    // analytic coords (matches reference _coordinates())
                    float x0u = (float)xi * 4.0f - 1.0f;
                    float y0u = (float)yi * 4.0f - 1.0f;
                    float cx0 = fmaxf(x0u, 0.0f);
                    float cy0 = fmaxf(y0u, 0.0f);
                    float cx1 = x0u + fh;
                    float cy1 = y0u + fw;
                    float area = (cx1 - cx0 + 1.0f) * (cy1 - cy0 + 1.0f);
                    bool alive = true;
                    for (int k = 0; k < pick; k++) {
                        float ltx = fmaxf(cx0, selx0[k]);
                        float lty = fmaxf(cy0, sely0[k]);
                        float rbx = fminf(cx1, selx1[k]);
                        float rby = fminf(cy1, sely1[k]);
                        float w = rbx - ltx + 1.0f;
                        float h = rby - lty + 1.0f;
                        float inter = (w < 0.0f || h < 0.0f) ? 0.0f : w * h;
                        float iou = inter / (area + selarea[k] - inter);
                        if (iou > thresh) alive = false;
                    }
                    if (alive && s > best) {   // per-thread gidx increases, so
                        best = s;              // strict > keeps smallest index
                        bidx = base + i;       // on equal scores
                    }
                }
            }

            // warp reduce: max score, tie -> min index
            #pragma unroll
            for (int o = 16; o > 0; o >>= 1) {
                float os = __shfl_down_sync(0xffffffffu, best, o);
                int   oi = __shfl_down_sync(0xffffffffu, bidx, o);
                if (os > best || (os == best && oi < bidx)) { best = os; bidx = oi; }
            }
            if (lane == 0) { red_s[warp] = best; red_i[warp] = bidx; }
            __syncthreads();

            if (tid == 0) {
                for (int w = 1; w < NTHREADS / 32; w++) {
                    float os = red_s[w]; int oi = red_i[w];
                    if (os > best || (os == best && oi < bidx)) { best = os; bidx = oi; }
                }
                // decode global window index -> ratio, (xi, yi) -> coords
                int rr = 0;
                #pragma unroll
                for (int r = 1; r < NRAT; r++) if (bidx >= BASE[r]) rr = r;
                int off = bidx - BASE[rr];
                int nc  = SATN - RW[rr];
                int xi  = off / nc;
                int yi  = off - xi * nc;
                float x0u = (float)xi * 4.0f - 1.0f;
                float y0u = (float)yi * 4.0f - 1.0f;
                float cx0 = fmaxf(x0u, 0.0f);
                float cy0 = fmaxf(y0u, 0.0f);
                float cx1 = x0u + 4.0f * RH[rr];
                float cy1 = y0u + 4.0f * RW[rr];
                selx0[pick] = cx0; sely0[pick] = cy0;
                selx1[pick] = cx1; sely1[pick] = cy1;
                selarea[pick] = (cx1 - cx0 + 1.0f) * (cy1 - cy0 + 1.0f);

                int slot = OUTOFF[g] + pick;
                out[b * PROPN + slot] = (float)bidx;                       // indices
                out[NBATCH * PROPN + b * PROPN + slot] = best;             // scores
            }
            __syncthreads();
        }
    }
}

extern "C" void kernel_launch(void* const* d_in, const int* in_sizes, int n_in,
                              void* d_out, int out_size) {
    const float* x = (const float*)d_in[0];
    float* out = (float*)d_out;
    (void)in_sizes; (void)n_in; (void)out_size;

    const int smem = SATN * SATN * (int)sizeof(float);  // 51076 B > 48KB default
    cudaFuncSetAttribute(appm_kernel, cudaFuncAttributeMaxDynamicSharedMemorySize, smem);
    appm_kernel<<<NBATCH, NTHREADS, smem>>>(x, out);
}

// round 3
// speedup vs baseline: 3.2790x; 3.2790x over previous
#include <cuda_runtime.h>
#include <math_constants.h>

// ---------------------------------------------------------------------------
// APPM: 13-ratio sliding-window average pooling over a 112x112 map (SAT in
// smem), then 3-group greedy NMS (picks 2/3/2, IoU 0.25), batch 256.
//
// Round-3 (= round-2 design, compile fixed): constexpr accessor FUNCTIONS
// instead of namespace constexpr arrays (device-visible without
// --expt-relaxed-constexpr).
//
// NMS per-eval cost cut via (a) exact integer IoU test with no division
// (5*inter > area+selarea), (b) separable per-(prior,ratio) shared tables
// wx5[xi], hy[yi] -> interior windows test with 2 LDS + FMUL + FSETP against
// a per-ratio constant, (c) scores re-read from gmem (coalesced, L2-hot),
// (d) group pick-0 argmax fused into the scoring pass.
//
// Output layout (float32):
//   [0,1792)               proposalN_indices  (256 x 7) as float
//   [1792,3584)            proposalN_windows_scores (256 x 7)
//   [3584, 3584+256*96981) window_scores (256 x 96981)
// ---------------------------------------------------------------------------

#define FEAT   112
#define SATN   113
#define NRAT   13
#define NBATCH 256
#define NTOTAL 96981
#define PROPN  7
#define NTH    1024
#define NXT    1121   // total per-prior entries for wx5 / hy tables

__host__ __device__ constexpr int cRH(int r) {
    constexpr int a[NRAT] = {16,12,20,24,20,28,32,24,40,28,40,28,36};
    return a[r];
}
__host__ __device__ constexpr int cRW(int r) {
    constexpr int a[NRAT] = {16,20,12,24,28,20,32,40,24,40,28,36,28};
    return a[r];
}
__host__ __device__ constexpr int cBASE(int r) {
    constexpr int a[NRAT+1] = {0,9409,18802,28195,36116,44021,51926,58487,
                               64984,71481,77686,83891,90436,96981};
    return a[r];
}
// prefix sums of nr = 113-RH and nc = 113-RW
__host__ __device__ constexpr int cXO(int r) {
    constexpr int a[NRAT] = {0,97,198,291,380,473,558,639,728,801,886,959,1044};
    return a[r];
}
__host__ __device__ constexpr int cYO(int r) {
    constexpr int a[NRAT] = {0,97,190,291,380,465,558,639,712,801,874,959,1036};
    return a[r];
}

// dynamic smem layout (floats): SAT[12769] | WX[2*1121] | HY[2*1121]
#define SMEM_FLOATS (12769 + 4*NXT)

// ---------------------------------------------------------------------------
// NMS scan over ratios [R0,R1) against P priors (P in {1,2}).
// Window suppressed by prior p iff 5*inter > area + selarea_p, where
// inter = wx[xi]*hy[yi] (wx pre-scaled by 5, both clamped >= 0). All values
// are exact small integers in fp32 -> decision identical to reference IoU.
// Interior windows (xi>=1 && yi>=1) have constant area -> constant RHS.
// ---------------------------------------------------------------------------
template<int R0, int R1, int P>
__device__ __forceinline__ void nms_scan(
    const float* __restrict__ ws, const float* __restrict__ WX,
    const float* __restrict__ HY, float sa0, float sa1, int tid,
    float& best, int& bidx)
{
    #pragma unroll
    for (int r = R0; r < R1; r++) {
        constexpr_helper:;
        const int rh = cRH(r), rw = cRW(r);
        const int nr = SATN - rh, nc = SATN - rw;
        const int base = cBASE(r);
        const float frh  = (float)(4 * rh),     frw  = (float)(4 * rw);
        const float frh1 = (float)(4 * rh + 1), frw1 = (float)(4 * rw + 1);
        const float* wx0 = WX + cXO(r);
        const float* hy0 = HY + cYO(r);
        const float* wx1 = WX + NXT + cXO(r);
        const float* hy1 = HY + NXT + cYO(r);
        const float rhs0 = frh1 * frw1 + sa0;
        const float rhs1 = frh1 * frw1 + sa1;

        // border row xi == 0 (includes corner yi == 0)
        for (int yi = tid; yi < nc; yi += NTH) {
            float s = ws[base + yi];
            float axay = frh * ((yi == 0) ? frw : frw1);
            bool sup = (wx0[0] * hy0[yi] > axay + sa0);
            if constexpr (P >= 2) sup |= (wx1[0] * hy1[yi] > axay + sa1);
            if (!sup && s > best) { best = s; bidx = base + yi; }
        }
        // border col yi == 0, xi >= 1
        for (int xi = 1 + tid; xi < nr; xi += NTH) {
            float s = ws[base + xi * nc];
            float axay = frh1 * frw;
            bool sup = (wx0[xi] * hy0[0] > axay + sa0);
            if constexpr (P >= 2) sup |= (wx1[xi] * hy1[0] > axay + sa1);
            if (!sup && s > best) { best = s; bidx = base + xi * nc; }
        }
        // interior: xi >= 1 && yi >= 1 (constant area per ratio)
        const int ncm = nc - 1;
        const int m = (nr - 1) * ncm;
        #pragma unroll 2
        for (int t = tid; t < m; t += NTH) {
            int xi = t / ncm + 1;            // ncm compile-time -> mul/shift
            int yi = t - (xi - 1) * ncm + 1;
            int w = base + xi * nc + yi;
            float s = ws[w];
            bool sup = (wx0[xi] * hy0[yi] > rhs0);
            if constexpr (P >= 2) sup |= (wx1[xi] * hy1[yi] > rhs1);
            if (!sup && s > best) { best = s; bidx = w; }
        }
    }
}

// ---------------------------------------------------------------------------
// CTA-wide (max score, min index on tie) reduction; writes outputs; if
// prior_slot >= 0, decodes winner coords into bsel/selarea.
// ---------------------------------------------------------------------------
__device__ __forceinline__ void select_pick(
    float best, int bidx, int tid, int lane, int warp, int b,
    float* __restrict__ out, int slot, int prior_slot,
    float* red_s, int* red_i, float* bsel, float* selarea)
{
    #pragma unroll
    for (int o = 16; o > 0; o >>= 1) {
        float os = __shfl_down_sync(0xffffffffu, best, o);
        int   oi = __shfl_down_sync(0xffffffffu, bidx, o);
        if (os > best || (os == best && oi < bidx)) { best = os; bidx = oi; }
    }
    if (lane == 0) { red_s[warp] = best; red_i[warp] = bidx; }
    __syncthreads();
    if (warp == 0) {
        best = red_s[lane]; bidx = red_i[lane];
        #pragma unroll
        for (int o = 16; o > 0; o >>= 1) {
            float os = __shfl_down_sync(0xffffffffu, best, o);
            int   oi = __shfl_down_sync(0xffffffffu, bidx, o);
            if (os > best || (os == best && oi < bidx)) { best = os; bidx = oi; }
        }
        if (lane == 0) {
            out[b * PROPN + slot] = (float)bidx;
            out[NBATCH * PROPN + b * PROPN + slot] = best;
            if (prior_slot >= 0) {
                int rh = cRH(0), rw = cRW(0), bb = 0;
                #pragma unroll
                for (int r = 1; r < NRAT; r++)
                    if (bidx >= cBASE(r)) { rh = cRH(r); rw = cRW(r); bb = cBASE(r); }
                int off = bidx - bb;
                int nc = SATN - rw;
                int xi = off / nc, yi = off - xi * nc;
                float x0u = (float)(4 * xi - 1), y0u = (float)(4 * yi - 1);
                float cx0 = fmaxf(x0u, 0.0f), cy0 = fmaxf(y0u, 0.0f);
                float cx1 = x0u + (float)(4 * rh);
                float cy1 = y0u + (float)(4 * rw);
                bsel[0] = cx0; bsel[1] = cy0; bsel[2] = cx1; bsel[3] = cy1;
                selarea[prior_slot] = (cx1 - cx0 + 1.0f) * (cy1 - cy0 + 1.0f);
            }
        }
    }
    __syncthreads();
}

// Fill wx5/hy suppression tables for prior `slot` over ratios [R0,R1).
template<int R0, int R1>
__device__ __forceinline__ void fill_prior(
    int slot, int tid, float* WX, float* HY, const float* bsel)
{
    float bx0 = bsel[0], by0 = bsel[1], bx1 = bsel[2], by1 = bsel[3];
    #pragma unroll
    for (int r = R0; r < R1; r++) {
        const int rh = cRH(r), rw = cRW(r);
        const int nr = SATN - rh, nc = SATN - rw;
        if (tid < nr) {
            float x0u = (float)tid * 4.0f - 1.0f;
            float x0 = fmaxf(x0u, 0.0f);
            float x1 = x0u + (float)(4 * rh);
            float w = fminf(x1, bx1) - fmaxf(x0, bx0) + 1.0f;
            WX[slot * NXT + cXO(r) + tid] = 5.0f * fmaxf(w, 0.0f);
        }
        if (tid < nc) {
            float y0u = (float)tid * 4.0f - 1.0f;
            float y0 = fmaxf(y0u, 0.0f);
            float y1 = y0u + (float)(4 * rw);
            float h = fminf(y1, by1) - fmaxf(y0, by0) + 1.0f;
            HY[slot * NXT + cYO(r) + tid] = fmaxf(h, 0.0f);
        }
    }
    __syncthreads();
}

__global__ void __launch_bounds__(NTH, 2)
appm_kernel(const float* __restrict__ x, float* __restrict__ out)
{
    extern __shared__ float SH[];
    float* S  = SH;                       // 12769 = 113*113 SAT
    float* WX = SH + 12769;               // 2 * NXT
    float* HY = WX + 2 * NXT;             // 2 * NXT

    __shared__ float red_s[32];
    __shared__ int   red_i[32];
    __shared__ float bsel[4];
    __shared__ float selarea[2];

    const int tid  = threadIdx.x;
    const int b    = blockIdx.x;
    const int lane = tid & 31;
    const int warp = tid >> 5;

    const float* __restrict__ xb = x + (size_t)b * (FEAT * FEAT);

    // ---- (1) SAT build ----------------------------------------------------
    for (int k = tid; k < SATN * SATN; k += NTH) {
        int i = k / SATN;
        int j = k - i * SATN;
        S[k] = (i > 0 && j > 0) ? xb[(i - 1) * FEAT + (j - 1)] : 0.0f;
    }
    __syncthreads();
    if (tid < SATN) {                      // row prefix (stride 113 = odd)
        float acc = 0.0f;
        float* row = S + tid * SATN;
        #pragma unroll 4
        for (int j = 1; j < SATN; j++) { acc += row[j]; row[j] = acc; }
    }
    __syncthreads();
    if (tid < SATN) {                      // column prefix (coalesced)
        float acc = 0.0f;
        #pragma unroll 4
        for (int i = 1; i < SATN; i++) {
            acc += S[i * SATN + tid];
            S[i * SATN + tid] = acc;
        }
    }
    __syncthreads();

    // ---- (2) window scores -> gmem, fused per-group argmax (pick 0) -------
    float* ws = out + 2 * (NBATCH * PROPN) + (size_t)b * NTOTAL;

    float best0 = -CUDART_INF_F, best1 = -CUDART_INF_F, best2 = -CUDART_INF_F;
    int   bi0 = 0x7fffffff, bi1 = 0x7fffffff, bi2 = 0x7fffffff;

    #pragma unroll
    for (int r = 0; r < NRAT; r++) {
        const int rh = cRH(r), rw = cRW(r);
        const int nr = SATN - rh, nc = SATN - rw;
        const int n  = nr * nc;
        const float inv = 1.0f / (float)(rh * rw);
        const int base = cBASE(r);
        const int coff = rh * SATN + rw;
        #pragma unroll 2
        for (int i = tid; i < n; i += NTH) {
            int xi = i / nc;               // nc compile-time -> mul/shift
            int yi = i - xi * nc;
            int a  = xi * SATN + yi;
            float s = (S[a + coff] - S[a + rw] - S[a + rh * SATN] + S[a]) * inv;
            ws[base + i] = s;
            if (r < 3)      { if (s > best0) { best0 = s; bi0 = base + i; } }
            else if (r < 6) { if (s > best1) { best1 = s; bi1 = base + i; } }
            else            { if (s > best2) { best2 = s; bi2 = base + i; } }
        }
    }
    // select_pick()'s first __syncthreads orders all ws stores before reads.

    float sa0, sa1;
    float nb; int ni;

    // ---- group 0: ratios [0,3), picks 2, out slots 0..1 --------------------
    select_pick(best0, bi0, tid, lane, warp, b, out, 0, 0, red_s, red_i, bsel, selarea);
    fill_prior<0, 3>(0, tid, WX, HY, bsel);
    sa0 = selarea[0];
    nb = -CUDART_INF_F; ni = 0x7fffffff;
    nms_scan<0, 3, 1>(ws, WX, HY, sa0, 0.0f, tid, nb, ni);
    select_pick(nb, ni, tid, lane, warp, b, out, 1, -1, red_s, red_i, bsel, selarea);

    // ---- group 1: ratios [3,6), picks 3, out slots 2..4 --------------------
    select_pick(best1, bi1, tid, lane, warp, b, out, 2, 0, red_s, red_i, bsel, selarea);
    fill_prior<3, 6>(0, tid, WX, HY, bsel);
    sa0 = selarea[0];
    nb = -CUDART_INF_F; ni = 0x7fffffff;
    nms_scan<3, 6, 1>(ws, WX, HY, sa0, 0.0f, tid, nb, ni);
    select_pick(nb, ni, tid, lane, warp, b, out, 3, 1, red_s, red_i, bsel, selarea);
    fill_prior<3, 6>(1, tid, WX, HY, bsel);
    sa1 = selarea[1];
    nb = -CUDART_INF_F; ni = 0x7fffffff;
    nms_scan<3, 6, 2>(ws, WX, HY, sa0, sa1, tid, nb, ni);
    select_pick(nb, ni, tid, lane, warp, b, out, 4, -1, red_s, red_i, bsel, selarea);

    // ---- group 2: ratios [6,13), picks 2, out slots 5..6 -------------------
    select_pick(best2, bi2, tid, lane, warp, b, out, 5, 0, red_s, red_i, bsel, selarea);
    fill_prior<6, 13>(0, tid, WX, HY, bsel);
    sa0 = selarea[0];
    nb = -CUDART_INF_F; ni = 0x7fffffff;
    nms_scan<6, 13, 1>(ws, WX, HY, sa0, 0.0f, tid, nb, ni);
    select_pick(nb, ni, tid, lane, warp, b, out, 6, -1, red_s, red_i, bsel, selarea);
}

extern "C" void kernel_launch(void* const* d_in, const int* in_sizes, int n_in,
                              void* d_out, int out_size) {
    const float* x = (const float*)d_in[0];
    float* out = (float*)d_out;
    (void)in_sizes; (void)n_in; (void)out_size;

    const int smem = SMEM_FLOATS * (int)sizeof(float);  // 68948 B
    cudaFuncSetAttribute(appm_kernel, cudaFuncAttributeMaxDynamicSharedMemorySize, smem);
    appm_kernel<<<NBATCH, NTH, smem>>>(x, out);
}

// round 4
// speedup vs baseline: 3.4189x; 1.0427x over previous
#include <cuda_runtime.h>
#include <math_constants.h>

// ---------------------------------------------------------------------------
// APPM: 13-ratio sliding-window avg pooling (smem SAT) + 3-group greedy NMS
// (picks 2/3/2, IoU 0.25), batch 256. Round-4: unroll-4 LDG batching in NMS,
// merged independent group scans, batched 3-way reductions (fewer syncs),
// trimmed index math.
//
// Output layout (float32):
//   [0,1792)               proposalN_indices  (256 x 7) as float
//   [1792,3584)            proposalN_windows_scores (256 x 7)
//   [3584, 3584+256*96981) window_scores (256 x 96981)
// ---------------------------------------------------------------------------

#define FEAT   112
#define SATN   113
#define NRAT   13
#define NBATCH 256
#define NTOTAL 96981
#define PROPN  7
#define NTH    1024
#define NXT    1121   // per-slot entries for wx5 / hy tables (all 13 ratios)

__host__ __device__ constexpr int cRH(int r) {
    constexpr int a[NRAT] = {16,12,20,24,20,28,32,24,40,28,40,28,36};
    return a[r];
}
__host__ __device__ constexpr int cRW(int r) {
    constexpr int a[NRAT] = {16,20,12,24,28,20,32,40,24,40,28,36,28};
    return a[r];
}
__host__ __device__ constexpr int cBASE(int r) {
    constexpr int a[NRAT+1] = {0,9409,18802,28195,36116,44021,51926,58487,
                               64984,71481,77686,83891,90436,96981};
    return a[r];
}
// prefix sums of nr = 113-RH and nc = 113-RW
__host__ __device__ constexpr int cXO(int r) {
    constexpr int a[NRAT] = {0,97,198,291,380,473,558,639,728,801,886,959,1044};
    return a[r];
}
__host__ __device__ constexpr int cYO(int r) {
    constexpr int a[NRAT] = {0,97,190,291,380,465,558,639,712,801,874,959,1036};
    return a[r];
}

// dynamic smem (floats): SAT[12769] | WX[2*NXT] | HY[2*NXT]
#define SMEM_FLOATS (12769 + 4*NXT)

__device__ __forceinline__ void argup(float s, int i, float& b, int& bi) {
    if (s > b) { b = s; bi = i; }   // per-thread visit order is increasing idx
}

// ---------------------------------------------------------------------------
// NMS scan over ratios [R0,R1), P priors (1 or 2). Suppress iff
// 5*inter > areaW + selarea (exact small ints in fp32 == reference IoU>0.25).
// Slot-0 tables hold the group's pick-0 prior; slot-1 holds g1's pick-1 prior.
// ---------------------------------------------------------------------------
template<int R0, int R1, int P>
__device__ __forceinline__ void nms_scan(
    const float* __restrict__ ws, const float* __restrict__ WX,
    const float* __restrict__ HY, float sa0, float sa1, int tid,
    float& best, int& bidx)
{
    #pragma unroll
    for (int r = R0; r < R1; r++) {
        const int rh = cRH(r), rw = cRW(r);
        const int nr = SATN - rh, nc = SATN - rw;
        const int base = cBASE(r);
        const float frh  = (float)(4 * rh),     frw  = (float)(4 * rw);
        const float frh1 = (float)(4 * rh + 1), frw1 = (float)(4 * rw + 1);
        const float* wx0 = WX + cXO(r);
        const float* hy0 = HY + cYO(r);
        const float* wx1 = WX + NXT + cXO(r);
        const float* hy1 = HY + NXT + cYO(r);
        const float rhs0 = frh1 * frw1 + sa0;
        const float rhs1 = frh1 * frw1 + sa1;
        const float* wsr = ws + base;

        // border row xi == 0 (includes corner yi == 0)
        for (int yi = tid; yi < nc; yi += NTH) {
            float s = wsr[yi];
            float axay = frh * ((yi == 0) ? frw : frw1);
            bool sup = (wx0[0] * hy0[yi] > axay + sa0);
            if constexpr (P >= 2) sup |= (wx1[0] * hy1[yi] > axay + sa1);
            if (!sup) argup(s, base + yi, best, bidx);
        }
        // border col yi == 0, xi >= 1
        for (int xi = 1 + tid; xi < nr; xi += NTH) {
            float s = wsr[xi * nc];
            float axay = frh1 * frw;
            bool sup = (wx0[xi] * hy0[0] > axay + sa0);
            if constexpr (P >= 2) sup |= (wx1[xi] * hy1[0] > axay + sa1);
            if (!sup) argup(s, base + xi * nc, best, bidx);
        }
        // interior: xi >= 1 && yi >= 1 (constant area -> constant RHS)
        const int ncm = nc - 1;
        const int m = (nr - 1) * ncm;
        int t = tid;
        #pragma unroll 1
        for (; t + 3 * NTH < m; t += 4 * NTH) {
            float s[4]; int xi[4]; int yi[4];
            #pragma unroll
            for (int u = 0; u < 4; u++) {
                int tt = t + u * NTH;
                xi[u] = tt / ncm + 1;              // ncm const -> mul/shift
                yi[u] = tt - (xi[u] - 1) * ncm + 1;
                // window idx - base = xi*nc + yi = tt + xi + ncm + 1
                s[u] = wsr[tt + xi[u] + ncm + 1];  // 4 LDG in flight
            }
            #pragma unroll
            for (int u = 0; u < 4; u++) {
                bool sup = (wx0[xi[u]] * hy0[yi[u]] > rhs0);
                if constexpr (P >= 2) sup |= (wx1[xi[u]] * hy1[yi[u]] > rhs1);
                if (!sup) argup(s[u], base + (t + u * NTH) + xi[u] + ncm + 1,
                                best, bidx);
            }
        }
        for (; t < m; t += NTH) {
            int xi = t / ncm + 1;
            int yi = t - (xi - 1) * ncm + 1;
            int w = t + xi + ncm + 1;
            float s = wsr[w];
            bool sup = (wx0[xi] * hy0[yi] > rhs0);
            if constexpr (P >= 2) sup |= (wx1[xi] * hy1[yi] > rhs1);
            if (!sup) argup(s, base + w, best, bidx);
        }
    }
}

// decode a winning window index into its box + area (lane0 only)
__device__ __forceinline__ void decode_box(int bidx, float* box, float* sa) {
    int rh = cRH(0), rw = cRW(0), bb = 0;
    #pragma unroll
    for (int r = 1; r < NRAT; r++)
        if (bidx >= cBASE(r)) { rh = cRH(r); rw = cRW(r); bb = cBASE(r); }
    int off = bidx - bb;
    int nc = SATN - rw;
    int xi = off / nc, yi = off - xi * nc;
    float x0u = (float)(4 * xi - 1), y0u = (float)(4 * yi - 1);
    float cx0 = fmaxf(x0u, 0.0f), cy0 = fmaxf(y0u, 0.0f);
    float cx1 = x0u + (float)(4 * rh);
    float cy1 = y0u + (float)(4 * rw);
    box[0] = cx0; box[1] = cy0; box[2] = cx1; box[3] = cy1;
    *sa = (cx1 - cx0 + 1.0f) * (cy1 - cy0 + 1.0f);
}

// warp-level pairwise merge (max score, min idx on tie)
__device__ __forceinline__ void wmerge(float& b, int& bi) {
    #pragma unroll
    for (int o = 16; o > 0; o >>= 1) {
        float os = __shfl_down_sync(0xffffffffu, b, o);
        int   oi = __shfl_down_sync(0xffffffffu, bi, o);
        if (os > b || (os == b && oi < bi)) { b = os; bi = oi; }
    }
}

// fill wx5/hy tables for ratios [R0,R1) into slot, from box (smem)
template<int R0, int R1>
__device__ __forceinline__ void fill_tables(
    int slot, int tid, float* WX, float* HY, const float* box)
{
    float bx0 = box[0], by0 = box[1], bx1 = box[2], by1 = box[3];
    #pragma unroll
    for (int r = R0; r < R1; r++) {
        const int rh = cRH(r), rw = cRW(r);
        const int nr = SATN - rh, nc = SATN - rw;
        if (tid < nr) {
            float x0u = (float)tid * 4.0f - 1.0f;
            float x0 = fmaxf(x0u, 0.0f);
            float x1 = x0u + (float)(4 * rh);
            float w = fminf(x1, bx1) - fmaxf(x0, bx0) + 1.0f;
            WX[slot * NXT + cXO(r) + tid] = 5.0f * fmaxf(w, 0.0f);
        }
        if (tid < nc) {
            float y0u = (float)tid * 4.0f - 1.0f;
            float y0 = fmaxf(y0u, 0.0f);
            float y1 = y0u + (float)(4 * rw);
            float h = fminf(y1, by1) - fmaxf(y0, by0) + 1.0f;
            HY[slot * NXT + cYO(r) + tid] = fmaxf(h, 0.0f);
        }
    }
}

__global__ void __launch_bounds__(NTH, 2)
appm_kernel(const float* __restrict__ x, float* __restrict__ out)
{
    extern __shared__ float SH[];
    float* S  = SH;                  // 12769 = 113*113 SAT
    float* WX = SH + 12769;          // 2 slots * NXT
    float* HY = WX + 2 * NXT;        // 2 slots * NXT

    __shared__ float red_s[3][32];
    __shared__ int   red_i[3][32];
    __shared__ float box[4][4];      // pick0 g0/g1/g2, g1-pick1
    __shared__ float sarea[4];

    const int tid  = threadIdx.x;
    const int b    = blockIdx.x;
    const int lane = tid & 31;
    const int warp = tid >> 5;

    const float* __restrict__ xb = x + (size_t)b * (FEAT * FEAT);

    // ---- (1) SAT build ----------------------------------------------------
    for (int k = tid; k < SATN * SATN; k += NTH) {
        int i = k / SATN;
        int j = k - i * SATN;
        S[k] = (i > 0 && j > 0) ? xb[(i - 1) * FEAT + (j - 1)] : 0.0f;
    }
    __syncthreads();
    if (tid < SATN) {                 // row prefix (stride 113 = odd)
        float acc = 0.0f;
        float* row = S + tid * SATN;
        #pragma unroll 4
        for (int j = 1; j < SATN; j++) { acc += row[j]; row[j] = acc; }
    }
    __syncthreads();
    if (tid < SATN) {                 // column prefix (coalesced)
        float acc = 0.0f;
        #pragma unroll 4
        for (int i = 1; i < SATN; i++) {
            acc += S[i * SATN + tid];
            S[i * SATN + tid] = acc;
        }
    }
    __syncthreads();

    // ---- (2) window scores -> gmem, fused per-group pick0 argmax ----------
    float* ws = out + 2 * (NBATCH * PROPN) + (size_t)b * NTOTAL;

    float bst[3] = {-CUDART_INF_F, -CUDART_INF_F, -CUDART_INF_F};
    int   bix[3] = {0x7fffffff, 0x7fffffff, 0x7fffffff};

    #pragma unroll
    for (int r = 0; r < NRAT; r++) {
        const int rh = cRH(r), rw = cRW(r);
        const int nc = SATN - rw;
        const int n  = (SATN - rh) * nc;
        const float inv = 1.0f / (float)(rh * rw);
        const int base = cBASE(r);
        const int g = (r < 3) ? 0 : (r < 6) ? 1 : 2;
        float* wsr = ws + base;
        int i = tid;
        #pragma unroll 1
        for (; i + 3 * NTH < n; i += 4 * NTH) {
            float sv[4];
            #pragma unroll
            for (int u = 0; u < 4; u++) {
                int ii = i + u * NTH;
                int xi = ii / nc;
                int a  = ii + xi * rw;       // = xi*113 + yi
                sv[u] = (S[a + rh * SATN + rw] - S[a + rw]
                       - S[a + rh * SATN] + S[a]) * inv;
            }
            #pragma unroll
            for (int u = 0; u < 4; u++) {
                int ii = i + u * NTH;
                wsr[ii] = sv[u];
                argup(sv[u], base + ii, bst[g], bix[g]);
            }
        }
        for (; i < n; i += NTH) {
            int xi = i / nc;
            int a  = i + xi * rw;
            float s = (S[a + rh * SATN + rw] - S[a + rw]
                     - S[a + rh * SATN] + S[a]) * inv;
            wsr[i] = s;
            argup(s, base + i, bst[g], bix[g]);
        }
    }

    // ---- (3a) batched 3-way reduction: pick0 of each group -----------------
    {
        #pragma unroll
        for (int g = 0; g < 3; g++) wmerge(bst[g], bix[g]);
        if (lane == 0)
            #pragma unroll
            for (int g = 0; g < 3; g++) { red_s[g][warp] = bst[g]; red_i[g][warp] = bix[g]; }
        __syncthreads();   // also orders all ws stores before NMS reads
        if (warp == 0) {
            float bb[3]; int ii[3];
            #pragma unroll
            for (int g = 0; g < 3; g++) { bb[g] = red_s[g][lane]; ii[g] = red_i[g][lane]; wmerge(bb[g], ii[g]); }
            if (lane == 0) {
                const int slot[3] = {0, 2, 5};
                #pragma unroll
                for (int g = 0; g < 3; g++) {
                    out[b * PROPN + slot[g]] = (float)ii[g];
                    out[NBATCH * PROPN + b * PROPN + slot[g]] = bb[g];
                    decode_box(ii[g], box[g], &sarea[g]);
                }
            }
        }
        __syncthreads();
    }

    // ---- (3b) fill slot-0 tables for all 3 groups' pick0 priors ------------
    fill_tables<0, 3>(0, tid, WX, HY, box[0]);
    fill_tables<3, 6>(0, tid, WX, HY, box[1]);
    fill_tables<6, 13>(0, tid, WX, HY, box[2]);
    __syncthreads();

    // ---- (3c) pick1 scans for all 3 groups (independent, no syncs) ---------
    float sa0 = sarea[0], sa1g = sarea[1], sa2 = sarea[2];
    bst[0] = bst[1] = bst[2] = -CUDART_INF_F;
    bix[0] = bix[1] = bix[2] = 0x7fffffff;
    nms_scan<0, 3, 1>(ws, WX, HY, sa0,  0.0f, tid, bst[0], bix[0]);
    nms_scan<3, 6, 1>(ws, WX, HY, sa1g, 0.0f, tid, bst[1], bix[1]);
    nms_scan<6, 13, 1>(ws, WX, HY, sa2, 0.0f, tid, bst[2], bix[2]);

    // ---- (3d) batched reduction: pick1s; decode only g1's winner -----------
    {
        #pragma unroll
        for (int g = 0; g < 3; g++) wmerge(bst[g], bix[g]);
        if (lane == 0)
            #pragma unroll
            for (int g = 0; g < 3; g++) { red_s[g][warp] = bst[g]; red_i[g][warp] = bix[g]; }
        __syncthreads();
        if (warp == 0) {
            float bb[3]; int ii[3];
            #pragma unroll
            for (int g = 0; g < 3; g++) { bb[g] = red_s[g][lane]; ii[g] = red_i[g][lane]; wmerge(bb[g], ii[g]); }
            if (lane == 0) {
                const int slot[3] = {1, 3, 6};
                #pragma unroll
                for (int g = 0; g < 3; g++) {
                    out[b * PROPN + slot[g]] = (float)ii[g];
                    out[NBATCH * PROPN + b * PROPN + slot[g]] = bb[g];
                }
                decode_box(ii[1], box[3], &sarea[3]);
            }
        }
        __syncthreads();
    }

    // ---- (3e) g1 pick2: fill slot-1 tables, scan with 2 priors -------------
    fill_tables<3, 6>(1, tid, WX, HY, box[3]);
    __syncthreads();
    float nb = -CUDART_INF_F; int ni = 0x7fffffff;
    nms_scan<3, 6, 2>(ws, WX, HY, sa1g, sarea[3], tid, nb, ni);
    {
        wmerge(nb, ni);
        if (lane == 0) { red_s[0][warp] = nb; red_i[0][warp] = ni; }
        __syncthreads();
        if (warp == 0) {
            nb = red_s[0][lane]; ni = red_i[0][lane];
            wmerge(nb, ni);
            if (lane == 0) {
                out[b * PROPN + 4] = (float)ni;
                out[NBATCH * PROPN + b * PROPN + 4] = nb;
            }
        }
    }
}

extern "C" void kernel_launch(void* const* d_in, const int* in_sizes, int n_in,
                              void* d_out, int out_size) {
    const float* x = (const float*)d_in[0];
    float* out = (float*)d_out;
    (void)in_sizes; (void)n_in; (void)out_size;

    const int smem = SMEM_FLOATS * (int)sizeof(float);  // 68948 B
    cudaFuncSetAttribute(appm_kernel, cudaFuncAttributeMaxDynamicSharedMemorySize, smem);
    appm_kernel<<<NBATCH, NTH, smem>>>(x, out);
}

// round 5
// speedup vs baseline: 3.5556x; 1.0400x over previous
#include <cuda_runtime.h>
#include <math_constants.h>

// ---------------------------------------------------------------------------
// APPM: 13-ratio sliding-window avg pooling (smem SAT) + 3-group greedy NMS
// (picks 2/3/2, IoU 0.25), batch 256.
//
// Round-5: SAT row stride padded to 116 -> all 4 corners of a 4-window tile
// load as aligned float4 (4 LDS.128 instead of 16 LDS.32). NMS yi>=1 grid has
// width (nc-1) % 4 == 0 -> float4 hy-table tiles; x-side suppression terms
// computed inline per row. LDGs batched ahead of ALU for MLP.
//
// Output layout (float32):
//   [0,1792)               proposalN_indices  (256 x 7) as float
//   [1792,3584)            proposalN_windows_scores (256 x 7)
//   [3584, 3584+256*96981) window_scores (256 x 96981)
// ---------------------------------------------------------------------------

#define FEAT   112
#define SATN   113
#define SATP   116            // padded SAT row stride (multiple of 4)
#define NRAT   13
#define NBATCH 256
#define NTOTAL 96981
#define PROPN  7
#define NTH    1024
#define NYS    1108           // per-slot hy-table length (sum of padded nc-1)

__host__ __device__ constexpr int cRH(int r) {
    constexpr int a[NRAT] = {16,12,20,24,20,28,32,24,40,28,40,28,36};
    return a[r];
}
__host__ __device__ constexpr int cRW(int r) {
    constexpr int a[NRAT] = {16,20,12,24,28,20,32,40,24,40,28,36,28};
    return a[r];
}
__host__ __device__ constexpr int cBASE(int r) {
    constexpr int a[NRAT+1] = {0,9409,18802,28195,36116,44021,51926,58487,
                               64984,71481,77686,83891,90436,96981};
    return a[r];
}
// prefix sums of (nc - 1) = 112 - RW  (all multiples of 4)
__host__ __device__ constexpr int cYS(int r) {
    constexpr int a[NRAT] = {0,96,188,288,376,460,552,632,704,792,864,948,1024};
    return a[r];
}

// dynamic smem (floats): SAT[113*116] | HYS[2*NYS]
#define SMEM_FLOATS (SATN*SATP + 2*NYS)

// index-aware arg-better (max score, min index on tie)
__device__ __forceinline__ void argb(float s, int i, float& b, int& bi) {
    if (s > b || (s == b && i < bi)) { b = s; bi = i; }
}

// warp-level pairwise merge (max score, min idx on tie)
__device__ __forceinline__ void wmerge(float& b, int& bi) {
    #pragma unroll
    for (int o = 16; o > 0; o >>= 1) {
        float os = __shfl_down_sync(0xffffffffu, b, o);
        int   oi = __shfl_down_sync(0xffffffffu, bi, o);
        if (os > b || (os == b && oi < bi)) { b = os; bi = oi; }
    }
}

// decode a winning window index into its box + area (lane0 only)
__device__ __forceinline__ void decode_box(int bidx, float* box, float* sa) {
    int rh = cRH(0), rw = cRW(0), bb = 0;
    #pragma unroll
    for (int r = 1; r < NRAT; r++)
        if (bidx >= cBASE(r)) { rh = cRH(r); rw = cRW(r); bb = cBASE(r); }
    int off = bidx - bb;
    int nc = SATN - rw;
    int xi = off / nc, yi = off - xi * nc;
    float x0u = (float)(4 * xi - 1), y0u = (float)(4 * yi - 1);
    float cx0 = fmaxf(x0u, 0.0f), cy0 = fmaxf(y0u, 0.0f);
    float cx1 = x0u + (float)(4 * rh);
    float cy1 = y0u + (float)(4 * rw);
    box[0] = cx0; box[1] = cy0; box[2] = cx1; box[3] = cy1;
    *sa = (cx1 - cx0 + 1.0f) * (cy1 - cy0 + 1.0f);
}

// fill hy table (yi >= 1 only; raw max(h,0)) for ratios [R0,R1) into slot
template<int R0, int R1>
__device__ __forceinline__ void fill_hys(
    int slot, int tid, float* HYS, const float* box)
{
    float by0 = box[1], by1 = box[3];
    #pragma unroll
    for (int r = R0; r < R1; r++) {
        const int rw = cRW(r);
        const int ncm = SATN - rw - 1;
        if (tid < ncm) {
            float y0 = (float)(4 * (tid + 1) - 1);       // yi>=1 -> no clamp
            float y1 = y0 + (float)(4 * rw);
            float h = fminf(y1, by1) - fmaxf(y0, by0) + 1.0f;
            HYS[slot * NYS + cYS(r) + tid] = fmaxf(h, 0.0f);
        }
    }
}

// ---------------------------------------------------------------------------
// NMS scan over ratios [R0,R1), P priors (1 or 2). Suppress iff
// 5*inter > areaW + selarea (exact small ints in fp32 == reference IoU>0.25).
// inter = w(xi)*h(yi), w computed inline per row, h from HYS table.
// ---------------------------------------------------------------------------
template<int R0, int R1, int P>
__device__ __forceinline__ void nms_scan(
    const float* __restrict__ ws, const float* __restrict__ HYS,
    float bx0a, float bx1a, float by0a, float by1a, float saA,
    float bx0b, float bx1b, float by0b, float by1b, float saB,
    int tid, float& best, int& bidx)
{
    #pragma unroll
    for (int r = R0; r < R1; r++) {
        const int rh = cRH(r), rw = cRW(r);
        const int nr = SATN - rh, nc = SATN - rw;
        const int ncm = nc - 1, nqm = ncm >> 2;
        const int base = cBASE(r);
        const float frh  = (float)(4 * rh),     frw  = (float)(4 * rw);
        const float frh1 = (float)(4 * rh + 1), frw1 = (float)(4 * rw + 1);
        const float* hys0 = HYS + cYS(r);
        const float* hys1 = HYS + NYS + cYS(r);
        const float* wsr = ws + base;

        // --- border column yi == 0 (ay = frw) ---
        // hy(yi=0): y0u=-1 -> y0=0, y1 = frw-1
        const float hb0 = fmaxf(fminf(frw - 1.0f, by1a) - fmaxf(0.0f, by0a) + 1.0f, 0.0f);
        float hb1 = 0.0f;
        if constexpr (P >= 2)
            hb1 = fmaxf(fminf(frw - 1.0f, by1b) - fmaxf(0.0f, by0b) + 1.0f, 0.0f);
        for (int xi = tid; xi < nr; xi += NTH) {
            float s = wsr[xi * nc];
            float x0u = (float)(4 * xi - 1);
            float x0 = fmaxf(x0u, 0.0f), x1 = x0u + frh;
            float ax = (xi == 0) ? frh : frh1;
            float w5a = 5.0f * fmaxf(fminf(x1, bx1a) - fmaxf(x0, bx0a) + 1.0f, 0.0f);
            bool sup = (w5a * hb0 > fmaf(ax, frw, saA));
            if constexpr (P >= 2) {
                float w5b = 5.0f * fmaxf(fminf(x1, bx1b) - fmaxf(x0, bx0b) + 1.0f, 0.0f);
                sup |= (w5b * hb1 > fmaf(ax, frw, saB));
            }
            if (!sup) argb(s, base + xi * nc, best, bidx);
        }

        // --- main grid: yi >= 1, 4-wide tiles (width ncm % 4 == 0) ---
        const int ntile = nr * nqm;
        #pragma unroll 1
        for (int t = tid; t < ntile; t += NTH) {
            int xi = t / nqm;                  // nqm const -> mul/shift
            int q  = t - xi * nqm;
            int yq = q << 2;
            int off = xi * nc + 1 + yq;
            // 4 coalesced score loads first (MLP), overlap with ALU below
            float s0 = wsr[off], s1 = wsr[off+1], s2 = wsr[off+2], s3 = wsr[off+3];
            float x0u = (float)(4 * xi - 1);
            float x0 = fmaxf(x0u, 0.0f), x1 = x0u + frh;
            float ax = (xi == 0) ? frh : frh1;
            float w5a = 5.0f * fmaxf(fminf(x1, bx1a) - fmaxf(x0, bx0a) + 1.0f, 0.0f);
            float rhsa = fmaf(ax, frw1, saA);
            float4 h4 = *(const float4*)(hys0 + yq);
            bool k0 = (w5a * h4.x <= rhsa);
            bool k1 = (w5a * h4.y <= rhsa);
            bool k2 = (w5a * h4.z <= rhsa);
            bool k3 = (w5a * h4.w <= rhsa);
            if constexpr (P >= 2) {
                float w5b = 5.0f * fmaxf(fminf(x1, bx1b) - fmaxf(x0, bx0b) + 1.0f, 0.0f);
                float rhsb = fmaf(ax, frw1, saB);
                float4 g4 = *(const float4*)(hys1 + yq);
                k0 &= (w5b * g4.x <= rhsb);
                k1 &= (w5b * g4.y <= rhsb);
                k2 &= (w5b * g4.z <= rhsb);
                k3 &= (w5b * g4.w <= rhsb);
            }
            if (k0) argb(s0, base + off,     best, bidx);
            if (k1) argb(s1, base + off + 1, best, bidx);
            if (k2) argb(s2, base + off + 2, best, bidx);
            if (k3) argb(s3, base + off + 3, best, bidx);
        }
    }
}

__global__ void __launch_bounds__(NTH, 2)
appm_kernel(const float* __restrict__ x, float* __restrict__ out)
{
    extern __shared__ float SH[];
    float* S   = SH;                    // SATN * SATP padded SAT
    float* HYS = SH + SATN * SATP;      // 2 slots * NYS

    __shared__ float red_s[3][32];
    __shared__ int   red_i[3][32];
    __shared__ float boxsm[4][4];       // pick0 g0/g1/g2, g1-pick1
    __shared__ float sarea[4];

    const int tid  = threadIdx.x;
    const int b    = blockIdx.x;
    const int lane = tid & 31;
    const int warp = tid >> 5;

    const float* __restrict__ xb = x + (size_t)b * (FEAT * FEAT);

    // ---- (1) SAT build (padded stride 116; cols 113-115 stay zero) --------
    for (int k = tid; k < SATN * SATP; k += NTH) {
        int i = k / SATP;
        int j = k - i * SATP;
        float v = 0.0f;
        if (i > 0 && j > 0 && j < SATN) v = xb[(i - 1) * FEAT + (j - 1)];
        S[k] = v;
    }
    __syncthreads();
    if (tid < SATN) {                   // row prefix
        float acc = 0.0f;
        float* row = S + tid * SATP;
        #pragma unroll 4
        for (int j = 1; j < SATN; j++) { acc += row[j]; row[j] = acc; }
    }
    __syncthreads();
    if (tid < SATN) {                   // column prefix (coalesced)
        float acc = 0.0f;
        #pragma unroll 4
        for (int i = 1; i < SATN; i++) {
            acc += S[i * SATP + tid];
            S[i * SATP + tid] = acc;
        }
    }
    __syncthreads();

    // ---- (2) window scores -> gmem via float4 SAT tiles, fused pick0 ------
    float* ws = out + 2 * (NBATCH * PROPN) + (size_t)b * NTOTAL;

    float bst[3] = {-CUDART_INF_F, -CUDART_INF_F, -CUDART_INF_F};
    int   bix[3] = {0x7fffffff, 0x7fffffff, 0x7fffffff};

    #pragma unroll
    for (int r = 0; r < NRAT; r++) {
        const int rh = cRH(r), rw = cRW(r);
        const int nr = SATN - rh, nc = SATN - rw;
        const int nq = (nc + 3) >> 2;   // last tile has exactly 1 window
        const int ntile = nr * nq;
        const float inv = 1.0f / (float)(rh * rw);
        const int base = cBASE(r);
        const int g = (r < 3) ? 0 : (r < 6) ? 1 : 2;
        const int R = rh * SATP;
        float* wsr = ws + base;
        #pragma unroll 1
        for (int t = tid; t < ntile; t += NTH) {
            int xi = t / nq;            // nq const -> mul/shift
            int q  = t - xi * nq;
            int yi = q << 2;
            int a  = xi * SATP + yi;    // 16B-aligned (116 and rw mult of 4)
            float4 v0 = *(const float4*)(S + a);
            float4 v1 = *(const float4*)(S + a + rw);
            float4 v2 = *(const float4*)(S + a + R);
            float4 v3 = *(const float4*)(S + a + R + rw);
            float s0 = (v3.x - v1.x - v2.x + v0.x) * inv;
            float s1 = (v3.y - v1.y - v2.y + v0.y) * inv;
            float s2 = (v3.z - v1.z - v2.z + v0.z) * inv;
            float s3 = (v3.w - v1.w - v2.w + v0.w) * inv;
            int off = xi * nc + yi;
            if (q != nq - 1) {
                wsr[off]     = s0;
                wsr[off + 1] = s1;
                wsr[off + 2] = s2;
                wsr[off + 3] = s3;
                // per-thread visit order ascending -> plain '>' keeps min idx
                if (s0 > bst[g]) { bst[g] = s0; bix[g] = base + off; }
                if (s1 > bst[g]) { bst[g] = s1; bix[g] = base + off + 1; }
                if (s2 > bst[g]) { bst[g] = s2; bix[g] = base + off + 2; }
                if (s3 > bst[g]) { bst[g] = s3; bix[g] = base + off + 3; }
            } else {
                wsr[off] = s0;
                if (s0 > bst[g]) { bst[g] = s0; bix[g] = base + off; }
            }
        }
    }

    // ---- (3a) batched 3-way reduction: pick0 of each group ----------------
    {
        #pragma unroll
        for (int g = 0; g < 3; g++) wmerge(bst[g], bix[g]);
        if (lane == 0)
            #pragma unroll
            for (int g = 0; g < 3; g++) { red_s[g][warp] = bst[g]; red_i[g][warp] = bix[g]; }
        __syncthreads();   // also orders ws stores before NMS reads
        if (warp == 0) {
            float bb[3]; int ii[3];
            #pragma unroll
            for (int g = 0; g < 3; g++) { bb[g] = red_s[g][lane]; ii[g] = red_i[g][lane]; wmerge(bb[g], ii[g]); }
            if (lane == 0) {
                const int slot[3] = {0, 2, 5};
                #pragma unroll
                for (int g = 0; g < 3; g++) {
                    out[b * PROPN + slot[g]] = (float)ii[g];
                    out[NBATCH * PROPN + b * PROPN + slot[g]] = bb[g];
                    decode_box(ii[g], boxsm[g], &sarea[g]);
                }
            }
        }
        __syncthreads();
    }

    // ---- (3b) hy tables (slot 0) for all 3 groups' pick0 priors ------------
    fill_hys<0, 3>(0, tid, HYS, boxsm[0]);
    fill_hys<3, 6>(0, tid, HYS, boxsm[1]);
    fill_hys<6, 13>(0, tid, HYS, boxsm[2]);
    __syncthreads();

    // ---- (3c) pick1 scans for all 3 groups (independent) -------------------
    float b0x0 = boxsm[0][0], b0y0 = boxsm[0][1], b0x1 = boxsm[0][2], b0y1 = boxsm[0][3];
    float b1x0 = boxsm[1][0], b1y0 = boxsm[1][1], b1x1 = boxsm[1][2], b1y1 = boxsm[1][3];
    float b2x0 = boxsm[2][0], b2y0 = boxsm[2][1], b2x1 = boxsm[2][2], b2y1 = boxsm[2][3];
    float sa0 = sarea[0], sa1g = sarea[1], sa2 = sarea[2];

    bst[0] = bst[1] = bst[2] = -CUDART_INF_F;
    bix[0] = bix[1] = bix[2] = 0x7fffffff;
    nms_scan<0, 3, 1>(ws, HYS, b0x0, b0x1, b0y0, b0y1, sa0,
                      0,0,0,0,0, tid, bst[0], bix[0]);
    nms_scan<3, 6, 1>(ws, HYS, b1x0, b1x1, b1y0, b1y1, sa1g,
                      0,0,0,0,0, tid, bst[1], bix[1]);
    nms_scan<6, 13, 1>(ws, HYS, b2x0, b2x1, b2y0, b2y1, sa2,
                       0,0,0,0,0, tid, bst[2], bix[2]);

    // ---- (3d) batched reduction: pick1s; decode only g1's winner -----------
    {
        #pragma unroll
        for (int g = 0; g < 3; g++) wmerge(bst[g], bix[g]);
        if (lane == 0)
            #pragma unroll
            for (int g = 0; g < 3; g++) { red_s[g][warp] = bst[g]; red_i[g][warp] = bix[g]; }
        __syncthreads();
        if (warp == 0) {
            float bb[3]; int ii[3];
            #pragma unroll
            for (int g = 0; g < 3; g++) { bb[g] = red_s[g][lane]; ii[g] = red_i[g][lane]; wmerge(bb[g], ii[g]); }
            if (lane == 0) {
                const int slot[3] = {1, 3, 6};
                #pragma unroll
                for (int g = 0; g < 3; g++) {
                    out[b * PROPN + slot[g]] = (float)ii[g];
                    out[NBATCH * PROPN + b * PROPN + slot[g]] = bb[g];
                }
                decode_box(ii[1], boxsm[3], &sarea[3]);
            }
        }
        __syncthreads();
    }

    // ---- (3e) g1 pick2: slot-1 tables, scan with 2 priors -------------------
    fill_hys<3, 6>(1, tid, HYS, boxsm[3]);
    __syncthreads();
    float b3x0 = boxsm[3][0], b3y0 = boxsm[3][1], b3x1 = boxsm[3][2], b3y1 = boxsm[3][3];
    float nb = -CUDART_INF_F; int ni = 0x7fffffff;
    nms_scan<3, 6, 2>(ws, HYS, b1x0, b1x1, b1y0, b1y1, sa1g,
                      b3x0, b3x1, b3y0, b3y1, sarea[3], tid, nb, ni);
    {
        wmerge(nb, ni);
        if (lane == 0) { red_s[0][warp] = nb; red_i[0][warp] = ni; }
        __syncthreads();
        if (warp == 0) {
            nb = red_s[0][lane]; ni = red_i[0][lane];
            wmerge(nb, ni);
            if (lane == 0) {
                out[b * PROPN + 4] = (float)ni;
                out[NBATCH * PROPN + b * PROPN + 4] = nb;
            }
        }
    }
}

extern "C" void kernel_launch(void* const* d_in, const int* in_sizes, int n_in,
                              void* d_out, int out_size) {
    const float* x = (const float*)d_in[0];
    float* out = (float*)d_out;
    (void)in_sizes; (void)n_in; (void)out_size;

    const int smem = SMEM_FLOATS * (int)sizeof(float);  // 61296 B
    cudaFuncSetAttribute(appm_kernel, cudaFuncAttributeMaxDynamicSharedMemorySize, smem);
    appm_kernel<<<NBATCH, NTH, smem>>>(x, out);
}

// round 6
// speedup vs baseline: 3.6095x; 1.0151x over previous
#include <cuda_runtime.h>
#include <math_constants.h>

// ---------------------------------------------------------------------------
// APPM: 13-ratio sliding-window avg pooling (smem SAT) + 3-group greedy NMS
// (picks 2/3/2, IoU 0.25), batch 256.
//
// Round-6: P=1 NMS scans recompute scores from the smem SAT (float4 corner
// loads, bit-identical expression) instead of LDG re-reads -> no gmem latency
// in NMS. hy suppression table extended to yi=0 so the NMS grid is the same
// aligned 4-wide tiling as scoring (float4 hy loads, no border loop).
//
// Output layout (float32):
//   [0,1792)               proposalN_indices  (256 x 7) as float
//   [1792,3584)            proposalN_windows_scores (256 x 7)
//   [3584, 3584+256*96981) window_scores (256 x 96981)
// ---------------------------------------------------------------------------

#define FEAT   112
#define SATN   113
#define SATP   116            // padded SAT row stride (multiple of 4)
#define NRAT   13
#define NBATCH 256
#define NTOTAL 96981
#define PROPN  7
#define NTH    1024
#define NYS    1160           // per-slot hy-table floats (padded nc summed)

__host__ __device__ constexpr int cRH(int r) {
    constexpr int a[NRAT] = {16,12,20,24,20,28,32,24,40,28,40,28,36};
    return a[r];
}
__host__ __device__ constexpr int cRW(int r) {
    constexpr int a[NRAT] = {16,20,12,24,28,20,32,40,24,40,28,36,28};
    return a[r];
}
__host__ __device__ constexpr int cBASE(int r) {
    constexpr int a[NRAT+1] = {0,9409,18802,28195,36116,44021,51926,58487,
                               64984,71481,77686,83891,90436,96981};
    return a[r];
}
// prefix sums of padded-to-4 nc (nc = 113-RW): {100,96,104,92,88,96,84,76,92,76,88,80,88}
__host__ __device__ constexpr int cYQ(int r) {
    constexpr int a[NRAT] = {0,100,196,300,392,480,576,660,736,828,904,992,1072};
    return a[r];
}

// dynamic smem (floats): SAT[113*116] | HYS[2*NYS]
#define SMEM_FLOATS (SATN*SATP + 2*NYS)

// index-aware arg-better (max score, min index on tie)
__device__ __forceinline__ void argb(float s, int i, float& b, int& bi) {
    if (s > b || (s == b && i < bi)) { b = s; bi = i; }
}

// warp-level pairwise merge (max score, min idx on tie)
__device__ __forceinline__ void wmerge(float& b, int& bi) {
    #pragma unroll
    for (int o = 16; o > 0; o >>= 1) {
        float os = __shfl_down_sync(0xffffffffu, b, o);
        int   oi = __shfl_down_sync(0xffffffffu, bi, o);
        if (os > b || (os == b && oi < bi)) { b = os; bi = oi; }
    }
}

// decode a winning window index into its box + area (lane0 only)
__device__ __forceinline__ void decode_box(int bidx, float* box, float* sa) {
    int rh = cRH(0), rw = cRW(0), bb = 0;
    #pragma unroll
    for (int r = 1; r < NRAT; r++)
        if (bidx >= cBASE(r)) { rh = cRH(r); rw = cRW(r); bb = cBASE(r); }
    int off = bidx - bb;
    int nc = SATN - rw;
    int xi = off / nc, yi = off - xi * nc;
    float x0u = (float)(4 * xi - 1), y0u = (float)(4 * yi - 1);
    float cx0 = fmaxf(x0u, 0.0f), cy0 = fmaxf(y0u, 0.0f);
    float cx1 = x0u + (float)(4 * rh);
    float cy1 = y0u + (float)(4 * rw);
    box[0] = cx0; box[1] = cy0; box[2] = cx1; box[3] = cy1;
    *sa = (cx1 - cx0 + 1.0f) * (cy1 - cy0 + 1.0f);
}

// fill hy table (full yi range incl. border yi=0; zero pad) for [R0,R1)
template<int R0, int R1>
__device__ __forceinline__ void fill_hys(
    int slot, int tid, float* HYS, const float* box)
{
    float by0 = box[1], by1 = box[3];
    #pragma unroll
    for (int r = R0; r < R1; r++) {
        const int rw = cRW(r);
        const int nc = SATN - rw;
        const int ncp = (nc + 3) & ~3;
        if (tid < ncp) {
            float h = 0.0f;
            if (tid < nc) {
                float y0u = (float)(4 * tid - 1);
                float y0 = fmaxf(y0u, 0.0f);
                float y1 = y0u + (float)(4 * rw);
                h = fmaxf(fminf(y1, by1) - fmaxf(y0, by0) + 1.0f, 0.0f);
            }
            HYS[slot * NYS + cYQ(r) + tid] = h;
        }
    }
}

// ---------------------------------------------------------------------------
// NMS scan, ratios [R0,R1). Suppress iff 5*inter > areaW + selarea (exact
// small ints in fp32 == reference IoU>0.25). inter = w(xi)*h(yi): w inline
// per row, h from HYS table (float4). RECOMP: scores recomputed from SAT via
// float4 (P=1 path, no gmem); else scalar LDG from ws (P=2 path, fewer regs).
// ---------------------------------------------------------------------------
template<int R0, int R1, int P, bool RECOMP>
__device__ __forceinline__ void nms_scan(
    const float* __restrict__ S, const float* __restrict__ ws,
    const float* __restrict__ HYS,
    float bx0a, float bx1a, float saA,
    float bx0b, float bx1b, float saB,
    int tid, float& best, int& bidx)
{
    #pragma unroll
    for (int r = R0; r < R1; r++) {
        const int rh = cRH(r), rw = cRW(r);
        const int nr = SATN - rh, nc = SATN - rw;
        const int nq = (nc + 3) >> 2;          // nc % 4 == 1: last tile = 1 win
        const int ntile = nr * nq;
        const int base = cBASE(r);
        const int R = rh * SATP;
        const float inv = 1.0f / (float)(rh * rw);
        const float frh  = (float)(4 * rh),     frw  = (float)(4 * rw);
        const float frh1 = frh + 1.0f,          frw1 = frw + 1.0f;
        const float* hys0 = HYS + cYQ(r);
        const float* hys1 = HYS + NYS + cYQ(r);
        const float* wsr = ws + base;

        #pragma unroll 1
        for (int t = tid; t < ntile; t += NTH) {
            int xi = t / nq;                   // nq const -> mul/shift
            int q  = t - xi * nq;
            int yq = q << 2;
            float s0, s1, s2, s3;
            if constexpr (RECOMP) {
                int a = xi * SATP + yq;        // 16B-aligned
                float4 v0 = *(const float4*)(S + a);
                float4 v1 = *(const float4*)(S + a + rw);
                float4 v2 = *(const float4*)(S + a + R);
                float4 v3 = *(const float4*)(S + a + R + rw);
                s0 = (v3.x - v1.x - v2.x + v0.x) * inv;
                s1 = (v3.y - v1.y - v2.y + v0.y) * inv;
                s2 = (v3.z - v1.z - v2.z + v0.z) * inv;
                s3 = (v3.w - v1.w - v2.w + v0.w) * inv;
            } else {
                int o = xi * nc + yq;
                s0 = wsr[o]; s1 = wsr[o+1]; s2 = wsr[o+2]; s3 = wsr[o+3];
            }
            float x0u = (float)(4 * xi - 1);
            float x0 = fmaxf(x0u, 0.0f), x1 = x0u + frh;
            float ax = (xi == 0) ? frh : frh1;
            float w5a = 5.0f * fmaxf(fminf(x1, bx1a) - fmaxf(x0, bx0a) + 1.0f, 0.0f);
            float rhsa  = fmaf(ax, frw1, saA);
            float rhsa0 = fmaf(ax, frw,  saA);     // yi == 0 (ay = frw)
            float4 h4 = *(const float4*)(hys0 + yq);
            bool k0 = (w5a * h4.x <= ((yq == 0) ? rhsa0 : rhsa));
            bool k1 = (w5a * h4.y <= rhsa);
            bool k2 = (w5a * h4.z <= rhsa);
            bool k3 = (w5a * h4.w <= rhsa);
            if constexpr (P >= 2) {
                float w5b = 5.0f * fmaxf(fminf(x1, bx1b) - fmaxf(x0, bx0b) + 1.0f, 0.0f);
                float rhsb  = fmaf(ax, frw1, saB);
                float rhsb0 = fmaf(ax, frw,  saB);
                float4 g4 = *(const float4*)(hys1 + yq);
                k0 &= (w5b * g4.x <= ((yq == 0) ? rhsb0 : rhsb));
                k1 &= (w5b * g4.y <= rhsb);
                k2 &= (w5b * g4.z <= rhsb);
                k3 &= (w5b * g4.w <= rhsb);
            }
            int off = base + xi * nc + yq;
            bool full = (q != nq - 1);
            if (k0)         argb(s0, off,     best, bidx);
            if (k1 && full) argb(s1, off + 1, best, bidx);
            if (k2 && full) argb(s2, off + 2, best, bidx);
            if (k3 && full) argb(s3, off + 3, best, bidx);
        }
    }
}

__global__ void __launch_bounds__(NTH, 2)
appm_kernel(const float* __restrict__ x, float* __restrict__ out)
{
    extern __shared__ float SH[];
    float* S   = SH;                    // SATN * SATP padded SAT
    float* HYS = SH + SATN * SATP;      // 2 slots * NYS

    __shared__ float red_s[3][32];
    __shared__ int   red_i[3][32];
    __shared__ float boxsm[4][4];       // pick0 g0/g1/g2, g1-pick1
    __shared__ float sarea[4];

    const int tid  = threadIdx.x;
    const int b    = blockIdx.x;
    const int lane = tid & 31;
    const int warp = tid >> 5;

    const float* __restrict__ xb = x + (size_t)b * (FEAT * FEAT);

    // ---- (1) SAT build (padded stride 116; cols 113-115 stay zero) --------
    for (int k = tid; k < SATN * SATP; k += NTH) {
        int i = k / SATP;
        int j = k - i * SATP;
        float v = 0.0f;
        if (i > 0 && j > 0 && j < SATN) v = xb[(i - 1) * FEAT + (j - 1)];
        S[k] = v;
    }
    __syncthreads();
    if (tid < SATN) {                   // row prefix
        float acc = 0.0f;
        float* row = S + tid * SATP;
        #pragma unroll 4
        for (int j = 1; j < SATN; j++) { acc += row[j]; row[j] = acc; }
    }
    __syncthreads();
    if (tid < SATN) {                   // column prefix (coalesced)
        float acc = 0.0f;
        #pragma unroll 4
        for (int i = 1; i < SATN; i++) {
            acc += S[i * SATP + tid];
            S[i * SATP + tid] = acc;
        }
    }
    __syncthreads();

    // ---- (2) window scores -> gmem via float4 SAT tiles, fused pick0 ------
    float* ws = out + 2 * (NBATCH * PROPN) + (size_t)b * NTOTAL;

    float bst[3] = {-CUDART_INF_F, -CUDART_INF_F, -CUDART_INF_F};
    int   bix[3] = {0x7fffffff, 0x7fffffff, 0x7fffffff};

    #pragma unroll
    for (int r = 0; r < NRAT; r++) {
        const int rh = cRH(r), rw = cRW(r);
        const int nr = SATN - rh, nc = SATN - rw;
        const int nq = (nc + 3) >> 2;
        const int ntile = nr * nq;
        const float inv = 1.0f / (float)(rh * rw);
        const int base = cBASE(r);
        const int g = (r < 3) ? 0 : (r < 6) ? 1 : 2;
        const int R = rh * SATP;
        float* wsr = ws + base;
        #pragma unroll 1
        for (int t = tid; t < ntile; t += NTH) {
            int xi = t / nq;
            int q  = t - xi * nq;
            int yi = q << 2;
            int a  = xi * SATP + yi;    // 16B-aligned
            float4 v0 = *(const float4*)(S + a);
            float4 v1 = *(const float4*)(S + a + rw);
            float4 v2 = *(const float4*)(S + a + R);
            float4 v3 = *(const float4*)(S + a + R + rw);
            float s0 = (v3.x - v1.x - v2.x + v0.x) * inv;
            float s1 = (v3.y - v1.y - v2.y + v0.y) * inv;
            float s2 = (v3.z - v1.z - v2.z + v0.z) * inv;
            float s3 = (v3.w - v1.w - v2.w + v0.w) * inv;
            int off = xi * nc + yi;
            if (q != nq - 1) {
                wsr[off]     = s0;
                wsr[off + 1] = s1;
                wsr[off + 2] = s2;
                wsr[off + 3] = s3;
                if (s0 > bst[g]) { bst[g] = s0; bix[g] = base + off; }
                if (s1 > bst[g]) { bst[g] = s1; bix[g] = base + off + 1; }
                if (s2 > bst[g]) { bst[g] = s2; bix[g] = base + off + 2; }
                if (s3 > bst[g]) { bst[g] = s3; bix[g] = base + off + 3; }
            } else {
                wsr[off] = s0;
                if (s0 > bst[g]) { bst[g] = s0; bix[g] = base + off; }
            }
        }
    }

    // ---- (3a) batched 3-way reduction: pick0 of each group ----------------
    {
        #pragma unroll
        for (int g = 0; g < 3; g++) wmerge(bst[g], bix[g]);
        if (lane == 0)
            #pragma unroll
            for (int g = 0; g < 3; g++) { red_s[g][warp] = bst[g]; red_i[g][warp] = bix[g]; }
        __syncthreads();
        if (warp == 0) {
            float bb[3]; int ii[3];
            #pragma unroll
            for (int g = 0; g < 3; g++) { bb[g] = red_s[g][lane]; ii[g] = red_i[g][lane]; wmerge(bb[g], ii[g]); }
            if (lane == 0) {
                const int slot[3] = {0, 2, 5};
                #pragma unroll
                for (int g = 0; g < 3; g++) {
                    out[b * PROPN + slot[g]] = (float)ii[g];
                    out[NBATCH * PROPN + b * PROPN + slot[g]] = bb[g];
                    decode_box(ii[g], boxsm[g], &sarea[g]);
                }
            }
        }
        __syncthreads();
    }

    // ---- (3b) hy tables (slot 0) for all 3 groups' pick0 priors ------------
    fill_hys<0, 3>(0, tid, HYS, boxsm[0]);
    fill_hys<3, 6>(0, tid, HYS, boxsm[1]);
    fill_hys<6, 13>(0, tid, HYS, boxsm[2]);
    __syncthreads();

    // ---- (3c) pick1 scans (SAT recompute path, no gmem) --------------------
    float b0x0 = boxsm[0][0], b0x1 = boxsm[0][2];
    float b1x0 = boxsm[1][0], b1x1 = boxsm[1][2];
    float b2x0 = boxsm[2][0], b2x1 = boxsm[2][2];
    float sa0 = sarea[0], sa1g = sarea[1], sa2 = sarea[2];

    bst[0] = bst[1] = bst[2] = -CUDART_INF_F;
    bix[0] = bix[1] = bix[2] = 0x7fffffff;
    nms_scan<0, 3, 1, true>(S, ws, HYS, b0x0, b0x1, sa0,
                            0, 0, 0, tid, bst[0], bix[0]);
    nms_scan<3, 6, 1, true>(S, ws, HYS, b1x0, b1x1, sa1g,
                            0, 0, 0, tid, bst[1], bix[1]);
    nms_scan<6, 13, 1, true>(S, ws, HYS, b2x0, b2x1, sa2,
                             0, 0, 0, tid, bst[2], bix[2]);

    // ---- (3d) batched reduction: pick1s; decode only g1's winner -----------
    {
        #pragma unroll
        for (int g = 0; g < 3; g++) wmerge(bst[g], bix[g]);
        if (lane == 0)
            #pragma unroll
            for (int g = 0; g < 3; g++) { red_s[g][warp] = bst[g]; red_i[g][warp] = bix[g]; }
        __syncthreads();
        if (warp == 0) {
            float bb[3]; int ii[3];
            #pragma unroll
            for (int g = 0; g < 3; g++) { bb[g] = red_s[g][lane]; ii[g] = red_i[g][lane]; wmerge(bb[g], ii[g]); }
            if (lane == 0) {
                const int slot[3] = {1, 3, 6};
                #pragma unroll
                for (int g = 0; g < 3; g++) {
                    out[b * PROPN + slot[g]] = (float)ii[g];
                    out[NBATCH * PROPN + b * PROPN + slot[g]] = bb[g];
                }
                decode_box(ii[1], boxsm[3], &sarea[3]);
            }
        }
        __syncthreads();
    }

    // ---- (3e) g1 pick2: slot-1 tables, 2-prior scan (LDG path, fewer regs) --
    fill_hys<3, 6>(1, tid, HYS, boxsm[3]);
    __syncthreads();
    float b3x0 = boxsm[3][0], b3x1 = boxsm[3][2];
    float nb = -CUDART_INF_F; int ni = 0x7fffffff;
    nms_scan<3, 6, 2, false>(S, ws, HYS, b1x0, b1x1, sa1g,
                             b3x0, b3x1, sarea[3], tid, nb, ni);
    {
        wmerge(nb, ni);
        if (lane == 0) { red_s[0][warp] = nb; red_i[0][warp] = ni; }
        __syncthreads();
        if (warp == 0) {
            nb = red_s[0][lane]; ni = red_i[0][lane];
            wmerge(nb, ni);
            if (lane == 0) {
                out[b * PROPN + 4] = (float)ni;
                out[NBATCH * PROPN + b * PROPN + 4] = nb;
            }
        }
    }
}

extern "C" void kernel_launch(void* const* d_in, const int* in_sizes, int n_in,
                              void* d_out, int out_size) {
    const float* x = (const float*)d_in[0];
    float* out = (float*)d_out;
    (void)in_sizes; (void)n_in; (void)out_size;

    const int smem = SMEM_FLOATS * (int)sizeof(float);  // 61712 B
    cudaFuncSetAttribute(appm_kernel, cudaFuncAttributeMaxDynamicSharedMemorySize, smem);
    appm_kernel<<<NBATCH, NTH, smem>>>(x, out);
}